// round 7
// baseline (speedup 1.0000x reference)
#include <cuda_runtime.h>
#include <math.h>

// ---------------------------------------------------------------------------
// EnhancedContrastiveLoss — v7: dual-pipe hybrid.
// ~80% of 128x128 sim blocks run tf32 mma.sync (tensor pipe), ~20% run a
// SIMT fp32 FFMA GEMM (fma pipe). With 2 CTAs/SM the two pipes saturate
// concurrently. Identical fused contrastive epilogue for both paths.
// ---------------------------------------------------------------------------

namespace {
constexpr int   NB   = 8192;
constexpr int   ND   = 256;
constexpr float TEMP = 0.07f;
constexpr float MRG  = 0.2f;
constexpr float NEGINF = -1e30f;
constexpr float CEXP = 20.609929059847869f;   // log2(e)/TEMP

constexpr int NBLK  = NB / 128;               // 64 row-blocks
constexpr int NPAIR = NBLK * (NBLK + 1) / 2;  // 2080 CTAs
constexpr int NTHR  = 256;
constexpr int OST   = 36;                     // HMMA operand smem row stride
constexpr int DST   = 129;                    // D-tile smem row stride
constexpr int NSTAGE = 3;
constexpr int FR    = 5;                      // 1 of FR blocks -> FFMA path
constexpr int FST   = 132;                    // FFMA transposed tile stride
constexpr int RED_BLOCKS = 256;

// dynamic smem layout (bytes) — HMMA path
constexpr int SM_OPA  = 0;                        // 3 x 18432 = 55296
constexpr int SM_OPB  = 55296;                    // 3 x 18432 = 55296
constexpr int SM_LABI = 110592;                   // 128 int
constexpr int SM_LABJ = 111104;                   // 128 int
constexpr int SMEM_TOTAL = 111616;
// FFMA path overlays: fAs [16][132] @0 (8448 B), fBs @8448 (8448 B)
// post-GEMM overlays: D tile 128x129 f32 @0 (66048 B), staging @66560 (12288 B)
constexpr int SM_STG  = 66560;
}

__device__ float g_en[NB * ND];                // normalized, tf32-rounded
__device__ int   g_lab[NB];
__device__ float g_part[6 * NBLK * NB];        // [q][slot][row]
__device__ float g_blk[RED_BLOCKS * 5];

// ----------------------------- helpers ------------------------------------
__device__ __forceinline__ unsigned smem_u32(const void* p) {
    unsigned a;
    asm("{ .reg .u64 t; cvta.to.shared.u64 t, %1; cvt.u32.u64 %0, t; }" : "=r"(a) : "l"(p));
    return a;
}
__device__ __forceinline__ void cpasync16(unsigned dst, const void* src) {
    asm volatile("cp.async.cg.shared.global [%0], [%1], 16;" :: "r"(dst), "l"(src) : "memory");
}
#define CP_COMMIT() asm volatile("cp.async.commit_group;" ::: "memory")
#define CP_WAIT0()  asm volatile("cp.async.wait_group 0;"  ::: "memory")
#define CP_WAIT1()  asm volatile("cp.async.wait_group 1;"  ::: "memory")

__device__ __forceinline__ void mma_tf32(float c[4], const unsigned a[4], const unsigned b[2]) {
    asm volatile(
        "mma.sync.aligned.m16n8k8.row.col.f32.tf32.tf32.f32 "
        "{%0,%1,%2,%3}, {%4,%5,%6,%7}, {%8,%9}, {%0,%1,%2,%3};"
        : "+f"(c[0]), "+f"(c[1]), "+f"(c[2]), "+f"(c[3])
        : "r"(a[0]), "r"(a[1]), "r"(a[2]), "r"(a[3]), "r"(b[0]), "r"(b[1]));
}

__device__ __forceinline__ float ex2f(float x) {
    float y; asm("ex2.approx.f32 %0, %1;" : "=f"(y) : "f"(x)); return y;
}
__device__ __forceinline__ void ins3(float& t0, float& t1, float& t2, float x) {
    float m;
    m = fmaxf(t0, x); x = fminf(t0, x); t0 = m;
    m = fmaxf(t1, x); x = fminf(t1, x); t1 = m;
    t2 = fmaxf(t2, x);
}

// ---------------------------------------------------------------------------
// Kernel 0: label dtype normalize (int64 vs int32 auto-detect)
// ---------------------------------------------------------------------------
__global__ void klab(const int* __restrict__ lab32) {
    __shared__ int s_nz;
    if (threadIdx.x == 0) s_nz = 0;
    __syncthreads();
    int acc = 0;
    for (int i = threadIdx.x; i < NB / 2; i += blockDim.x) acc |= lab32[2 * i + 1];
    if (acc) atomicOr(&s_nz, 1);
    __syncthreads();
    const bool is64 = (s_nz == 0);
    for (int i = threadIdx.x; i < NB; i += blockDim.x)
        g_lab[i] = is64 ? lab32[2 * i] : lab32[i];
}

// ---------------------------------------------------------------------------
// Kernel 1: L2 normalize + round-to-nearest-tf32
// ---------------------------------------------------------------------------
__global__ void knorm(const float* __restrict__ emb) {
    int gw   = (blockIdx.x * blockDim.x + threadIdx.x) >> 5;
    int lane = threadIdx.x & 31;
    if (gw >= NB) return;
    const float4* src = reinterpret_cast<const float4*>(emb + (size_t)gw * ND);
    float4 v0 = src[lane * 2];
    float4 v1 = src[lane * 2 + 1];
    float ss = v0.x*v0.x + v0.y*v0.y + v0.z*v0.z + v0.w*v0.w
             + v1.x*v1.x + v1.y*v1.y + v1.z*v1.z + v1.w*v1.w;
    #pragma unroll
    for (int o = 16; o > 0; o >>= 1) ss += __shfl_xor_sync(0xffffffffu, ss, o);
    float inv = 1.0f / fmaxf(sqrtf(ss), 1e-12f);
    float f[8] = {v0.x*inv, v0.y*inv, v0.z*inv, v0.w*inv,
                  v1.x*inv, v1.y*inv, v1.z*inv, v1.w*inv};
    #pragma unroll
    for (int i = 0; i < 8; i++) {
        unsigned b;
        asm("cvt.rna.tf32.f32 %0, %1;" : "=r"(b) : "f"(f[i]));
        f[i] = __uint_as_float(b);
    }
    float4* dst = reinterpret_cast<float4*>(g_en + (size_t)gw * ND);
    dst[lane * 2]     = make_float4(f[0], f[1], f[2], f[3]);
    dst[lane * 2 + 1] = make_float4(f[4], f[5], f[6], f[7]);
}

// ---------------------------------------------------------------------------
// Kernel 2: hybrid GEMM (HMMA or FFMA per block) + two-view fused epilogue.
// ---------------------------------------------------------------------------
__global__ void __launch_bounds__(NTHR, 2) kmain() {
    extern __shared__ char smem[];
    float* Ds   = (float*)smem;                 // overlays operands post-GEMM
    float* stg  = (float*)(smem + SM_STG);
    int*   labI = (int*)(smem + SM_LABI);
    int*   labJ = (int*)(smem + SM_LABJ);

    const int tid  = threadIdx.x;

    // map linear block id -> (I, J), I <= J
    int I = 0, rem = blockIdx.x;
    while (rem >= NBLK - I) { rem -= NBLK - I; I++; }
    const int J = I + rem;
    const int rowI = I * 128, rowJ = J * 128;
    const bool diag = (I == J);
    const bool ffma_path = (!diag) && ((blockIdx.x % FR) == 2);

    // labels into smem
    if (tid < 128) labI[tid] = g_lab[rowI + tid];
    else           labJ[tid - 128] = g_lab[rowJ + tid - 128];

    if (ffma_path) {
        // ================= FFMA path (fma pipe) =================
        // v2-style core: transposed tiles fAs[k][row], 16x16 threads, 8x8 rtile.
        float* fAs = (float*)smem;              // [16][132]
        float* fBs = (float*)(smem + 8448);     // [16][132]
        const int ty = tid >> 4, tx = tid & 15;

        float facc[8][8];
        #pragma unroll
        for (int i = 0; i < 8; i++)
            #pragma unroll
            for (int j = 0; j < 8; j++) facc[i][j] = 0.f;

        for (int kc = 0; kc < ND; kc += 16) {
            __syncthreads();                    // previous chunk readers done
            #pragma unroll
            for (int i2 = 0; i2 < 2; i2++) {
                int idx = tid + i2 * NTHR;      // 0..511
                int r = idx >> 2, kq = (idx & 3) * 4;
                float4 va = *reinterpret_cast<const float4*>(
                    g_en + (size_t)(rowI + r) * ND + kc + kq);
                fAs[(kq+0)*FST + r] = va.x; fAs[(kq+1)*FST + r] = va.y;
                fAs[(kq+2)*FST + r] = va.z; fAs[(kq+3)*FST + r] = va.w;
                float4 vb = *reinterpret_cast<const float4*>(
                    g_en + (size_t)(rowJ + r) * ND + kc + kq);
                fBs[(kq+0)*FST + r] = vb.x; fBs[(kq+1)*FST + r] = vb.y;
                fBs[(kq+2)*FST + r] = vb.z; fBs[(kq+3)*FST + r] = vb.w;
            }
            __syncthreads();
            #pragma unroll
            for (int kk = 0; kk < 16; kk++) {
                float a[8], b[8];
                float4 a0 = *reinterpret_cast<const float4*>(&fAs[kk*FST + ty*8]);
                float4 a1 = *reinterpret_cast<const float4*>(&fAs[kk*FST + ty*8 + 4]);
                float4 b0 = *reinterpret_cast<const float4*>(&fBs[kk*FST + tx*8]);
                float4 b1 = *reinterpret_cast<const float4*>(&fBs[kk*FST + tx*8 + 4]);
                a[0]=a0.x; a[1]=a0.y; a[2]=a0.z; a[3]=a0.w;
                a[4]=a1.x; a[5]=a1.y; a[6]=a1.z; a[7]=a1.w;
                b[0]=b0.x; b[1]=b0.y; b[2]=b0.z; b[3]=b0.w;
                b[4]=b1.x; b[5]=b1.y; b[6]=b1.z; b[7]=b1.w;
                #pragma unroll
                for (int i = 0; i < 8; i++)
                    #pragma unroll
                    for (int j = 0; j < 8; j++)
                        facc[i][j] = fmaf(a[i], b[j], facc[i][j]);
            }
        }
        __syncthreads();                        // all reads done before Ds writes
        #pragma unroll
        for (int i = 0; i < 8; i++)
            #pragma unroll
            for (int j = 0; j < 8; j++)
                Ds[(size_t)(ty*8 + i) * DST + tx*8 + j] = facc[i][j];
    } else {
        // ================= HMMA path (tensor pipe) =================
        float* OpA = (float*)(smem + SM_OPA);
        float* OpB = (float*)(smem + SM_OPB);
        const unsigned sbA = smem_u32(OpA), sbB = smem_u32(OpB);
        const int lane  = tid & 31;
        const int wid   = tid >> 5;
        const int warpM = wid >> 2;          // 0..1
        const int warpN = wid & 3;           // 0..3
        const int qrow  = lane >> 2;         // 0..7
        const int qcol  = lane & 3;          // 0..3

        auto issue = [&](int g) {
            const int stage = g % NSTAGE;
            const int kc = g * 32;
            #pragma unroll
            for (int q = 0; q < 4; q++) {
                int idx = tid + q * NTHR;        // 0..1023
                int r = idx >> 3, f = (idx & 7) * 4;
                unsigned off = (unsigned)((stage * 128 + r) * OST + f) * 4u;
                cpasync16(sbA + off, g_en + (size_t)(rowI + r) * ND + kc + f);
                if (!diag)
                    cpasync16(sbB + off, g_en + (size_t)(rowJ + r) * ND + kc + f);
            }
            CP_COMMIT();
        };

        float acc[4][4][4];
        #pragma unroll
        for (int i = 0; i < 4; i++)
            #pragma unroll
            for (int j = 0; j < 4; j++)
                #pragma unroll
                for (int c = 0; c < 4; c++) acc[i][j][c] = 0.f;

        issue(0); issue(1);

        for (int g = 0; g < 8; g++) {
            if (g < 7) CP_WAIT1();
            else       CP_WAIT0();
            __syncthreads();
            if (g + 2 < 8) issue(g + 2);

            const int stage = g % NSTAGE;
            const float* Apan = OpA + stage * 128 * OST;
            const float* Bpan = diag ? Apan : OpB + stage * 128 * OST;
            #pragma unroll
            for (int ks = 0; ks < 4; ks++) {
                const int kb = ks * 8;
                unsigned a[4][4], b[4][2];
                #pragma unroll
                for (int i = 0; i < 4; i++) {
                    const float* ap = Apan + (size_t)(warpM * 64 + i * 16 + qrow) * OST + kb + qcol;
                    a[i][0] = __float_as_uint(ap[0]);
                    a[i][1] = __float_as_uint(ap[8 * OST]);
                    a[i][2] = __float_as_uint(ap[4]);
                    a[i][3] = __float_as_uint(ap[8 * OST + 4]);
                }
                #pragma unroll
                for (int j = 0; j < 4; j++) {
                    const float* bp = Bpan + (size_t)(warpN * 32 + j * 8 + qrow) * OST + kb + qcol;
                    b[j][0] = __float_as_uint(bp[0]);
                    b[j][1] = __float_as_uint(bp[4]);
                }
                #pragma unroll
                for (int i = 0; i < 4; i++)
                    #pragma unroll
                    for (int j = 0; j < 4; j++)
                        mma_tf32(acc[i][j], a[i], b[j]);
            }
        }
        __syncthreads();                        // GEMM done; operand smem dead

        #pragma unroll
        for (int i = 0; i < 4; i++) {
            #pragma unroll
            for (int j = 0; j < 4; j++) {
                const int rl0 = warpM * 64 + i * 16 + qrow;
                const int cl0 = warpN * 32 + j * 8 + 2 * qcol;
                Ds[(size_t)rl0 * DST + cl0]           = acc[i][j][0];
                Ds[(size_t)rl0 * DST + cl0 + 1]       = acc[i][j][1];
                Ds[(size_t)(rl0 + 8) * DST + cl0]     = acc[i][j][2];
                Ds[(size_t)(rl0 + 8) * DST + cl0 + 1] = acc[i][j][3];
            }
        }
    }
    __syncthreads();

    // ---- task-parallel epilogue: 512 tasks = {view, half, idx} ----
    const int rounds = diag ? 1 : 2;
    for (int rr = 0; rr < rounds; rr++) {
        const int tau  = tid + rr * 256;
        const int view = tau >> 8;
        const int half = (tau >> 7) & 1;
        const int idx  = tau & 127;
        float sA = 0.f, sP = 0.f, pm = NEGINF;
        float t0 = NEGINF, t1 = NEGINF, t2 = NEGINF;
        if (view == 0) {
            const int lr = labI[idx];
            const float* dr = Ds + (size_t)idx * DST + half * 64;
            #pragma unroll 4
            for (int c = 0; c < 64; c++) {
                float d = dr[c];
                const int col = half * 64 + c;
                if (!(diag && col == idx)) {
                    float E = ex2f(d * CEXP);
                    sA += E;
                    if (lr == labJ[col]) { sP += E; pm = fmaxf(pm, d); }
                    else ins3(t0, t1, t2, d);
                }
            }
        } else {
            const int lc = labJ[idx];
            #pragma unroll 4
            for (int r = 0; r < 64; r++) {
                float d = Ds[(size_t)(half * 64 + r) * DST + idx];
                float E = ex2f(d * CEXP);
                sA += E;
                if (lc == labI[half * 64 + r]) { sP += E; pm = fmaxf(pm, d); }
                else ins3(t0, t1, t2, d);
            }
        }
        float* p = stg + (size_t)tau * 6;
        p[0] = sA; p[1] = sP; p[2] = pm; p[3] = t0; p[4] = t1; p[5] = t2;
    }
    __syncthreads();

    // ---- merge halves and write g_part ----
    if (tid < 128 || !diag) {
        const int view = tid >> 7;
        const int idx  = tid & 127;
        const float* p0 = stg + (size_t)(view * 256 + idx) * 6;
        const float* p1 = p0 + 128 * 6;
        float sA = p0[0] + p1[0];
        float sP = p0[1] + p1[1];
        float pm = fmaxf(p0[2], p1[2]);
        float t0 = p0[3], t1 = p0[4], t2 = p0[5];
        ins3(t0, t1, t2, p1[3]); ins3(t0, t1, t2, p1[4]); ins3(t0, t1, t2, p1[5]);
        const int slot = view ? I : J;
        const int grow = (view ? rowJ : rowI) + idx;
        g_part[(size_t)(0 * NBLK + slot) * NB + grow] = sA;
        g_part[(size_t)(1 * NBLK + slot) * NB + grow] = sP;
        g_part[(size_t)(2 * NBLK + slot) * NB + grow] = pm;
        g_part[(size_t)(3 * NBLK + slot) * NB + grow] = t0;
        g_part[(size_t)(4 * NBLK + slot) * NB + grow] = t1;
        g_part[(size_t)(5 * NBLK + slot) * NB + grow] = t2;
    }
}

// ---------------------------------------------------------------------------
// Kernel 3: per-row merge of 64 slot partials (8 threads/row) + loss terms.
// ---------------------------------------------------------------------------
__global__ void krow() {
    const int gid = blockIdx.x * blockDim.x + threadIdx.x;
    const int row = gid >> 3;
    const int sl  = (gid & 7) * 8;
    float sA = 0.f, sP = 0.f, pm = NEGINF;
    float t0 = NEGINF, t1 = NEGINF, t2 = NEGINF;
    #pragma unroll
    for (int s = 0; s < 8; s++) {
        const int slot = sl + s;
        sA += g_part[(size_t)(0 * NBLK + slot) * NB + row];
        sP += g_part[(size_t)(1 * NBLK + slot) * NB + row];
        pm  = fmaxf(pm, g_part[(size_t)(2 * NBLK + slot) * NB + row]);
        ins3(t0, t1, t2, g_part[(size_t)(3 * NBLK + slot) * NB + row]);
        ins3(t0, t1, t2, g_part[(size_t)(4 * NBLK + slot) * NB + row]);
        ins3(t0, t1, t2, g_part[(size_t)(5 * NBLK + slot) * NB + row]);
    }
    #pragma unroll
    for (int o = 1; o <= 4; o <<= 1) {
        sA += __shfl_xor_sync(0xffffffffu, sA, o);
        sP += __shfl_xor_sync(0xffffffffu, sP, o);
        pm  = fmaxf(pm, __shfl_xor_sync(0xffffffffu, pm, o));
        float o0 = __shfl_xor_sync(0xffffffffu, t0, o);
        float o1 = __shfl_xor_sync(0xffffffffu, t1, o);
        float o2 = __shfl_xor_sync(0xffffffffu, t2, o);
        ins3(t0, t1, t2, o0); ins3(t0, t1, t2, o1); ins3(t0, t1, t2, o2);
    }

    float basic = 0.f, h = 0.f, m = 0.f, hp = 0.f, v = 0.f;
    if ((threadIdx.x & 7) == 0 && pm > -1e29f) {
        hp = 1.f;
        basic = -logf(sP / (sA + 1e-10f) + 1e-10f);
        float pms   = pm * (1.f / TEMP);
        float mean3 = (t0 + t1 + t2) * (1.f / (3.f * TEMP));
        h = fmaxf(mean3 - pms + MRG, 0.f);
        if (t0 > -1e29f) {
            v = 1.f;
            m = fmaxf(t0 * (1.f / TEMP) - pms + MRG, 0.f);
        }
    }

    __shared__ float red[5][8];
    float vals[5] = {basic, h, m, hp, v};
    int lane = threadIdx.x & 31, warp = threadIdx.x >> 5;
    #pragma unroll
    for (int q = 0; q < 5; q++) {
        float x = vals[q];
        #pragma unroll
        for (int o = 16; o > 0; o >>= 1) x += __shfl_xor_sync(0xffffffffu, x, o);
        if (lane == 0) red[q][warp] = x;
    }
    __syncthreads();
    if (warp == 0 && lane == 0) {
        #pragma unroll
        for (int q = 0; q < 5; q++) {
            float x = 0.f;
            #pragma unroll
            for (int w = 0; w < 8; w++) x += red[q][w];
            g_blk[blockIdx.x * 5 + q] = x;
        }
    }
}

// ---------------------------------------------------------------------------
// Kernel 4: final scalar.
// ---------------------------------------------------------------------------
__global__ void kfin(float* __restrict__ out, int n) {
    int lane = threadIdx.x;   // 32 threads
    float acc[5];
    #pragma unroll
    for (int q = 0; q < 5; q++) {
        float x = 0.f;
        for (int i = lane; i < RED_BLOCKS; i += 32) x += g_blk[i * 5 + q];
        #pragma unroll
        for (int o = 16; o > 0; o >>= 1) x += __shfl_xor_sync(0xffffffffu, x, o);
        acc[q] = x;
    }
    float Bv = acc[0], Hv = acc[1], Mv = acc[2], HP = acc[3], V = acc[4];
    float n_hp = fmaxf(HP, 1.f);
    float n_v  = fmaxf(V, 1.f);
    float margin_loss = (V > 0.f) ? (Mv / n_v) : 0.f;
    float total = Bv / n_hp + 0.5f * (Hv / n_hp) + 0.1f * margin_loss;
    for (int i = lane; i < n; i += 32) out[i] = total;
}

// ---------------------------------------------------------------------------
extern "C" void kernel_launch(void* const* d_in, const int* in_sizes, int n_in,
                              void* d_out, int out_size) {
    const float* emb   = (const float*)d_in[0];
    const int*   lab32 = (const int*)d_in[1];
    (void)in_sizes; (void)n_in;

    cudaFuncSetAttribute(kmain, cudaFuncAttributeMaxDynamicSharedMemorySize, SMEM_TOTAL);

    klab<<<1, 256>>>(lab32);
    knorm<<<NB * 32 / 256, 256>>>(emb);
    kmain<<<NPAIR, NTHR, SMEM_TOTAL>>>();
    krow<<<RED_BLOCKS, 256>>>();
    kfin<<<1, 32>>>((float*)d_out, out_size);
}